// round 15
// baseline (speedup 1.0000x reference)
#include <cuda_runtime.h>
#include <math.h>

#define TT 256
#define DD 512
#define HH 256
#define EE 256
#define VV 8192
#define G3 768           // 3*H
#define DH (DD*HH)

// Scratch (static device globals; no runtime allocation).
__device__ float g_P[2][(size_t)VV * G3];   // emb@Wih^T + biases, [sel][v][3H]
__device__ int   g_perm[TT * DD];           // per-step bucketed row ids
__device__ int   g_cnt1[TT];                // grp1 count per step
__device__ int   g_e_is_i32;
__device__ unsigned int g_arr8[8 * 32];     // per-column arrive counters, 128B apart
__device__ unsigned int g_pad[31];          // keep g_epoch on its own 128B line
__device__ unsigned int g_epoch  = 0;       // bumped once per column per step (8/step)

// ---------------------------------------------------------------------------
// Packed f32x2 helpers
// ---------------------------------------------------------------------------
__device__ __forceinline__ unsigned long long dup2(float b) {
    unsigned long long r;
    asm("mov.b64 %0, {%1, %1};" : "=l"(r) : "r"(__float_as_uint(b)));
    return r;
}
__device__ __forceinline__ void fma2(unsigned long long& acc, unsigned long long a, unsigned long long b) {
    asm("fma.rn.f32x2 %0, %1, %2, %0;" : "+l"(acc) : "l"(a), "l"(b));
}
__device__ __forceinline__ void add2(unsigned long long& acc, unsigned long long o) {
    asm("add.rn.f32x2 %0, %0, %1;" : "+l"(acc) : "l"(o));
}
__device__ __forceinline__ float lo32(unsigned long long v) {
    unsigned int l, h; asm("mov.b64 {%0, %1}, %2;" : "=r"(l), "=r"(h) : "l"(v));
    return __uint_as_float(l);
}
__device__ __forceinline__ float hi32(unsigned long long v) {
    unsigned int l, h; asm("mov.b64 {%0, %1}, %2;" : "=r"(l), "=r"(h) : "l"(v));
    return __uint_as_float(h);
}
__device__ __forceinline__ unsigned int atom_add_acqrel(unsigned int* p) {
    unsigned int o;
    asm volatile("atom.add.acq_rel.gpu.u32 %0, [%1], 1;" : "=r"(o) : "l"(p) : "memory");
    return o;
}
__device__ __forceinline__ unsigned int ld_acquire(const unsigned int* p) {
    unsigned int v;
    asm volatile("ld.acquire.gpu.u32 %0, [%1];" : "=r"(v) : "l"(p) : "memory");
    return v;
}
__device__ __forceinline__ float fast_sigmoid(float x) {
    return 1.f / (1.f + __expf(-x));
}
__device__ __forceinline__ float fast_tanh(float x) {
    return 1.f - 2.f / (__expf(2.f * x) + 1.f);   // exact limits at +-inf, no NaN
}

// ---------------------------------------------------------------------------
__global__ void detect_edges_kernel(const unsigned char* __restrict__ e) {
    int i32 = 1;
    for (int k = 0; k < 256; ++k)
        if (e[4 * k + 1] | e[4 * k + 2] | e[4 * k + 3]) { i32 = 0; break; }
    g_e_is_i32 = i32;
}

__global__ void bucket_kernel(const void* __restrict__ edges) {
    int t = threadIdx.x;
    if (t >= TT) return;
    const int is_i32 = g_e_is_i32;
    const unsigned char* e8  = (const unsigned char*)edges + (size_t)t * DD;
    const int*           e32 = (const int*)edges + (size_t)t * DD;
    int* p = g_perm + (size_t)t * DD;
    int i1 = 0, i0 = 0;
    for (int d = 0; d < DD; ++d) {
        bool ev = is_i32 ? (e32[d] != 0) : (e8[d] != 0);
        if (ev) p[i1++] = d;
        else    p[DD - 1 - (i0++)] = d;
    }
    g_cnt1[t] = i1;
}

// ---------------------------------------------------------------------------
// P[sel][v][j] = dot(emb[v], Wih[j]) + bih[j] + (j < 2H ? bhh[j] : 0)
// 64x64 tile, 256 threads, 4x4 microtile, f32x2-packed row pairs.
// Double-buffered K-tiles: next tile's LDGs staged in registers during the
// current tile's FMA block; one __syncthreads per tile.
// ---------------------------------------------------------------------------
__global__ void precompute_P_kernel(
    const float* __restrict__ emb,
    const float* __restrict__ cWih, const float* __restrict__ cbih, const float* __restrict__ cbhh,
    const float* __restrict__ sWih, const float* __restrict__ sbih, const float* __restrict__ sbhh)
{
    int sel = blockIdx.z;
    const float* Wih = sel ? cWih : sWih;
    const float* bih = sel ? cbih : sbih;
    const float* bhh = sel ? cbhh : sbhh;
    float* P = g_P[sel];

    __shared__ __align__(16) float As[2][32][64];
    __shared__ __align__(16) float Bs[2][32][64];

    int vbase = blockIdx.y * 64;
    int jbase = blockIdx.x * 64;
    int tid  = threadIdx.x;
    int rowg = tid >> 4;
    int colg = tid & 15;

    // per-thread staging coords (2 float4 per matrix)
    int m_[2], k4_[2];
#pragma unroll
    for (int i = 0; i < 2; ++i) {
        int lin = tid + i * 256;
        m_[i]  = lin >> 3;
        k4_[i] = (lin & 7) << 2;
    }

    unsigned long long acc[2][4];
#pragma unroll
    for (int i = 0; i < 2; ++i)
#pragma unroll
        for (int j = 0; j < 4; ++j) acc[i][j] = 0ull;

    // stage tile 0 into buf 0
    float4 ra[2], rb[2];
#pragma unroll
    for (int i = 0; i < 2; ++i) {
        ra[i] = *(const float4*)&emb[(size_t)(vbase + m_[i]) * EE + k4_[i]];
        rb[i] = *(const float4*)&Wih[(size_t)(jbase + m_[i]) * EE + k4_[i]];
    }
#pragma unroll
    for (int i = 0; i < 2; ++i) {
        As[0][k4_[i] + 0][m_[i]] = ra[i].x; As[0][k4_[i] + 1][m_[i]] = ra[i].y;
        As[0][k4_[i] + 2][m_[i]] = ra[i].z; As[0][k4_[i] + 3][m_[i]] = ra[i].w;
        Bs[0][k4_[i] + 0][m_[i]] = rb[i].x; Bs[0][k4_[i] + 1][m_[i]] = rb[i].y;
        Bs[0][k4_[i] + 2][m_[i]] = rb[i].z; Bs[0][k4_[i] + 3][m_[i]] = rb[i].w;
    }
    __syncthreads();

    for (int kt = 0; kt < 8; ++kt) {
        int cb = kt & 1;
        if (kt < 7) {
            int kb = (kt + 1) * 32;
#pragma unroll
            for (int i = 0; i < 2; ++i) {
                ra[i] = *(const float4*)&emb[(size_t)(vbase + m_[i]) * EE + kb + k4_[i]];
                rb[i] = *(const float4*)&Wih[(size_t)(jbase + m_[i]) * EE + kb + k4_[i]];
            }
        }
#pragma unroll 8
        for (int k = 0; k < 32; ++k) {
            ulonglong2 av = *(const ulonglong2*)&As[cb][k][rowg * 4];
            float4 b = *(const float4*)&Bs[cb][k][colg * 4];
            unsigned long long b0 = dup2(b.x), b1 = dup2(b.y), b2 = dup2(b.z), b3 = dup2(b.w);
            fma2(acc[0][0], av.x, b0); fma2(acc[1][0], av.y, b0);
            fma2(acc[0][1], av.x, b1); fma2(acc[1][1], av.y, b1);
            fma2(acc[0][2], av.x, b2); fma2(acc[1][2], av.y, b2);
            fma2(acc[0][3], av.x, b3); fma2(acc[1][3], av.y, b3);
        }
        if (kt < 7) {
            int nb = cb ^ 1;
#pragma unroll
            for (int i = 0; i < 2; ++i) {
                As[nb][k4_[i] + 0][m_[i]] = ra[i].x; As[nb][k4_[i] + 1][m_[i]] = ra[i].y;
                As[nb][k4_[i] + 2][m_[i]] = ra[i].z; As[nb][k4_[i] + 3][m_[i]] = ra[i].w;
                Bs[nb][k4_[i] + 0][m_[i]] = rb[i].x; Bs[nb][k4_[i] + 1][m_[i]] = rb[i].y;
                Bs[nb][k4_[i] + 2][m_[i]] = rb[i].z; Bs[nb][k4_[i] + 3][m_[i]] = rb[i].w;
            }
            __syncthreads();
        }
    }

#pragma unroll
    for (int i = 0; i < 2; ++i) {
        int v0 = vbase + rowg * 4 + i * 2;
#pragma unroll
        for (int j = 0; j < 4; ++j) {
            int jj = jbase + colg * 4 + j;
            float bias = bih[jj] + (jj < 2 * HH ? bhh[jj] : 0.f);
            P[(size_t)v0 * G3 + jj]       = lo32(acc[i][j]) + bias;
            P[(size_t)(v0 + 1) * G3 + jj] = hi32(acc[i][j]) + bias;
        }
    }
}

extern __shared__ float dyn_smem[];

// ---------------------------------------------------------------------------
// Persistent recurrent kernel (R14 structure; barrier release chain flattened
// by one level: column leader bumps g_epoch directly, poll target 8*(t+1)).
// Grid (8 u-tiles, 17 slots) = 136 blocks.
// ---------------------------------------------------------------------------
__global__ void __launch_bounds__(512, 1) persistent_kernel(
    const float* __restrict__ h0,              // [D,H]
    float* __restrict__ out,                   // [T,D,H]
    const int* __restrict__ nodes,             // [T,D]
    const float* __restrict__ cWhh, const float* __restrict__ cbhh,
    const float* __restrict__ sWhh, const float* __restrict__ sbhh)
{
    float* sB = dyn_smem;                       // [2][256][96]
    float* sA = dyn_smem + 2 * 256 * 96;        // [256][32] swizzled; bufs overlay
    unsigned long long* sPq = (unsigned long long*)sA;

    __shared__ int Rs[2][32];
    __shared__ int Ns[2][32];
    __shared__ unsigned char Vs[2][32];
    __shared__ float s_bnb[2][32];
    __shared__ unsigned int s_e0;

    int tid   = threadIdx.x;
    int u0    = blockIdx.x * 32;
    int slot  = blockIdx.y;
    int q     = tid >> 7;          // K-quarter 0..3
    int qtid  = tid & 127;
    int rowg  = qtid >> 5;         // rows rowg*8..+7
    int colg  = qtid & 31;         // cols colg*3..+2
    int r8    = rowg * 8;
    int qoff  = q << 6;

    // Base epoch read at kernel start. Safe: a column needs its 17 blocks to
    // finish the multi-microsecond prologue + step 0 before it can bump
    // g_epoch; wave-1 launch spread is far smaller, so no bump can precede
    // any block's first instruction.
    if (tid == 0) s_e0 = *(volatile unsigned int*)&g_epoch;

    // ---- prologue: load both Whh slices into smem (once) ----
    for (int g = 0; g < 2; ++g) {
        const float* W = g ? cWhh : sWhh;
        for (int idx = tid; idx < 96 * 64; idx += 512) {
            int c  = idx >> 6;
            int k4 = (idx & 63) << 2;
            int wr = ((c >> 5) << 8) + u0 + (c & 31);
            float4 v = *(const float4*)&W[(size_t)wr * HH + k4];
            float* b = sB + ((size_t)g * 256 + k4) * 96 + c;
            b[0 * 96] = v.x; b[1 * 96] = v.y; b[2 * 96] = v.z; b[3 * 96] = v.w;
        }
    }
    if (tid < 64) {
        int g = tid >> 5, ui = tid & 31;
        s_bnb[g][ui] = (g ? cbhh : sbhh)[2 * HH + u0 + ui];
    }

    // epilogue element assignment: elems e = tid, tid+512 -> rows em0/em1, unit eu
    int em0 = tid >> 5;            // 0..15
    int em1 = em0 + 16;            // 16..31
    int eu  = tid & 31;

    // packed-buffer float offsets (constant per thread):
    // C(m,c) float index = (m>>3)*832 + (c/3)*26 + (c%3)*8 + ((m&7)>>1)*2 + (m&1)
    int gof[3];
#pragma unroll
    for (int g = 0; g < 3; ++g) {
        int c  = g * 32 + eu;
        int cD = c / 3;
        int cM = c - 3 * cD;
        gof[g] = cD * 26 + cM * 8;
    }
    int r0of = (em0 >> 3) * 832 + ((em0 & 7) >> 1) * 2 + (em0 & 1);
    int r1of = (em1 >> 3) * 832 + ((em1 & 7) >> 1) * 2 + (em1 & 1);

    // ---- meta for t = 0 ----
    bool act; int grp;
    {
        int cnt1 = g_cnt1[0];
        int n1 = (cnt1 + 31) >> 5;
        int n0 = (DD - cnt1 + 31) >> 5;
        int pbase = 0;
        if (slot < n1)           { act = true;  grp = 1; pbase = slot * 32; }
        else if (slot < n1 + n0) { act = true;  grp = 0; pbase = DD - (slot - n1 + 1) * 32; }
        else                      { act = false; grp = 0; }
        if (act && tid < 32) {
            int p = pbase + tid;
            bool v = grp ? (p < cnt1) : (p >= cnt1);
            int pp = v ? p : (grp ? 0 : DD - 1);
            int d = g_perm[pp];
            Rs[0][tid] = d;
            Ns[0][tid] = nodes[d];
            Vs[0][tid] = v ? 1 : 0;
        }
    }
    __syncthreads();
    unsigned int e0 = s_e0;

    for (int t = 0; t < TT; ++t) {
        int cur = t & 1;
        const float* h_prev = (t == 0) ? h0 : (out + (size_t)(t - 1) * DH);
        float*       h_out  = out + (size_t)t * DH;

        // next-step activity (cheap ALU; LDGs issued later, post-combine)
        int tn = t + 1;
        bool act2 = false; int grp2 = 0; int pbase2 = 0; int cnt1n = 0;
        if (tn < TT) {
            cnt1n = g_cnt1[tn];
            int n1 = (cnt1n + 31) >> 5;
            int n0 = (DD - cnt1n + 31) >> 5;
            if (slot < n1)           { act2 = true; grp2 = 1; pbase2 = slot * 32; }
            else if (slot < n1 + n0) { act2 = true; grp2 = 0; pbase2 = DD - (slot - n1 + 1) * 32; }
        }

        if (act) {
            // ---- prefetch epilogue operands (overlap with gather + k-loop) ----
            const float* P = g_P[grp];
            const float* Pp0 = P + (size_t)Ns[cur][em0] * G3 + u0;
            const float* Pp1 = P + (size_t)Ns[cur][em1] * G3 + u0;
            float pf_gr0 = __ldg(Pp0 + eu);
            float pf_gz0 = __ldg(Pp0 + HH + eu);
            float pf_gn0 = __ldg(Pp0 + 2 * HH + eu);
            float pf_gr1 = __ldg(Pp1 + eu);
            float pf_gz1 = __ldg(Pp1 + HH + eu);
            float pf_gn1 = __ldg(Pp1 + 2 * HH + eu);
            float pf_hp0 = __ldg(h_prev + (size_t)Rs[cur][em0] * HH + u0 + eu);
            float pf_hp1 = __ldg(h_prev + (size_t)Rs[cur][em1] * HH + u0 + eu);

            // ---- per-quarter gather: 32 rows x 64 k of this quarter ----
#pragma unroll
            for (int i = 0; i < 4; ++i) {
                int lin = i * 128 + qtid;        // 0..511 : 32 rows x 16 float4
                int m   = lin >> 4;
                int k   = qoff + ((lin & 15) << 2);
                float4 v = *(const float4*)&h_prev[(size_t)Rs[cur][m] * HH + k];
                int ms = m ^ (k & 28);
                sA[(k + 0) * 32 + ms] = v.x;
                sA[(k + 1) * 32 + ms] = v.y;
                sA[(k + 2) * 32 + ms] = v.z;
                sA[(k + 3) * 32 + ms] = v.w;
            }
            asm volatile("bar.sync %0, 128;" :: "r"(1 + q) : "memory");

            // ---- split-K x4 FFMA2 loop: this quarter does K=64 ----
            const float* Apt = sA + qoff * 32;
            const float* Bpt = sB + (size_t)grp * (256 * 96) + qoff * 96 + colg * 3;
            unsigned long long acc[3][4];   // [col][row-pair]
#pragma unroll
            for (int jj = 0; jj < 3; ++jj)
#pragma unroll
                for (int p = 0; p < 4; ++p) acc[jj][p] = 0ull;
#pragma unroll 32
            for (int kk = 0; kk < 64; ++kk) {
                int sw = kk & 28;               // compile-time per unrolled slot
                ulonglong2 a01 = *(const ulonglong2*)(Apt + kk * 32 + (r8 ^ sw));
                ulonglong2 a23 = *(const ulonglong2*)(Apt + kk * 32 + ((r8 + 4) ^ sw));
                const float* b = Bpt + kk * 96;
                unsigned long long b0 = dup2(b[0]);
                unsigned long long b1 = dup2(b[1]);
                unsigned long long b2 = dup2(b[2]);
                fma2(acc[0][0], a01.x, b0); fma2(acc[0][1], a01.y, b0);
                fma2(acc[0][2], a23.x, b0); fma2(acc[0][3], a23.y, b0);
                fma2(acc[1][0], a01.x, b1); fma2(acc[1][1], a01.y, b1);
                fma2(acc[1][2], a23.x, b1); fma2(acc[1][3], a23.y, b1);
                fma2(acc[2][0], a01.x, b2); fma2(acc[2][1], a01.y, b2);
                fma2(acc[2][2], a23.x, b2); fma2(acc[2][3], a23.y, b2);
            }
            __syncthreads();     // all sA reads done before buffer overlay

            // ---- combine: q1/q3 write, then q0/q2 add+write, epilogue sums ----
            unsigned long long* bufA = sPq;          // [128][13] u64
            unsigned long long* bufB = sPq + 1664;
            if (q == 1) {
                unsigned long long* wp = bufA + qtid * 13;
#pragma unroll
                for (int jj = 0; jj < 3; ++jj)
#pragma unroll
                    for (int p = 0; p < 4; ++p) wp[jj * 4 + p] = acc[jj][p];
            } else if (q == 3) {
                unsigned long long* wp = bufB + qtid * 13;
#pragma unroll
                for (int jj = 0; jj < 3; ++jj)
#pragma unroll
                    for (int p = 0; p < 4; ++p) wp[jj * 4 + p] = acc[jj][p];
            }
            __syncthreads();
            if (q == 0) {
                unsigned long long* rw = bufA + qtid * 13;
#pragma unroll
                for (int jj = 0; jj < 3; ++jj)
#pragma unroll
                    for (int p = 0; p < 4; ++p) { add2(acc[jj][p], rw[jj * 4 + p]); rw[jj * 4 + p] = acc[jj][p]; }
            } else if (q == 2) {
                unsigned long long* rw = bufB + qtid * 13;
#pragma unroll
                for (int jj = 0; jj < 3; ++jj)
#pragma unroll
                    for (int p = 0; p < 4; ++p) { add2(acc[jj][p], rw[jj * 4 + p]); rw[jj * 4 + p] = acc[jj][p]; }
            }
            __syncthreads();

            // ---- t+1 meta LDGs issued here: latency overlaps the epilogue ----
            if (act2 && tid < 32) {
                int p = pbase2 + tid;
                bool v = grp2 ? (p < cnt1n) : (p >= cnt1n);
                int pp = v ? p : (grp2 ? 0 : DD - 1);
                int d = g_perm[(size_t)tn * DD + pp];
                Rs[tn & 1][tid] = d;
                Ns[tn & 1][tid] = nodes[(size_t)tn * DD + d];
                Vs[tn & 1][tid] = v ? 1 : 0;
            }

            // ---- GRU gate epilogue: C = bufA + bufB, 2 elems per thread ----
            const float* bufAf = (const float*)bufA;
            const float* bufBf = (const float*)bufB;
            if (Vs[cur][em0]) {
                float hr = bufAf[r0of + gof[0]] + bufBf[r0of + gof[0]];
                float hz = bufAf[r0of + gof[1]] + bufBf[r0of + gof[1]];
                float hn = bufAf[r0of + gof[2]] + bufBf[r0of + gof[2]] + s_bnb[grp][eu];
                float r = fast_sigmoid(pf_gr0 + hr);
                float z = fast_sigmoid(pf_gz0 + hz);
                float n = fast_tanh(pf_gn0 + r * hn);
                h_out[(size_t)Rs[cur][em0] * HH + u0 + eu] = (1.f - z) * n + z * pf_hp0;
            }
            if (Vs[cur][em1]) {
                float hr = bufAf[r1of + gof[0]] + bufBf[r1of + gof[0]];
                float hz = bufAf[r1of + gof[1]] + bufBf[r1of + gof[1]];
                float hn = bufAf[r1of + gof[2]] + bufBf[r1of + gof[2]] + s_bnb[grp][eu];
                float r = fast_sigmoid(pf_gr1 + hr);
                float z = fast_sigmoid(pf_gz1 + hz);
                float n = fast_tanh(pf_gn1 + r * hn);
                h_out[(size_t)Rs[cur][em1] * HH + u0 + eu] = (1.f - z) * n + z * pf_hp1;
            }
        } else {
            // inactive this step: still load next-step meta
            if (act2 && tid < 32) {
                int p = pbase2 + tid;
                bool v = grp2 ? (p < cnt1n) : (p >= cnt1n);
                int pp = v ? p : (grp2 ? 0 : DD - 1);
                int d = g_perm[(size_t)tn * DD + pp];
                Rs[tn & 1][tid] = d;
                Ns[tn & 1][tid] = nodes[(size_t)tn * DD + d];
                Vs[tn & 1][tid] = v ? 1 : 0;
            }
        }
        __syncthreads();    // epilogue reads/stores done + next meta visible

        // ---- flattened acq_rel grid barrier (skip after final step) ----
        // Column leader (17th arriver) bumps g_epoch directly; poll for
        // 8 bumps per step. One fewer L2 atomic on the release chain.
        if (t < TT - 1) {
            if (tid == 0) {
                unsigned int o = atom_add_acqrel(&g_arr8[blockIdx.x * 32]);
                if (o == 16) {                          // last of 17 in this column
                    g_arr8[blockIdx.x * 32] = 0;        // ordered by next release-RMW
                    atom_add_acqrel(&g_epoch);
                }
                while (ld_acquire(&g_epoch) - e0 < 8u * (unsigned int)(t + 1)) { }
            }
            __syncthreads();
        }
        act = act2; grp = grp2;
    }
}

// ---------------------------------------------------------------------------
extern "C" void kernel_launch(void* const* d_in, const int* in_sizes, int n_in,
                              void* d_out, int out_size) {
    const int*           nodes = (const int*)d_in[0];
    const void*          edges = d_in[1];
    const float*         h0    = (const float*)d_in[2];
    const float*         emb   = (const float*)d_in[3];
    const float*         cWih  = (const float*)d_in[4];
    const float*         cWhh  = (const float*)d_in[5];
    const float*         cbih  = (const float*)d_in[6];
    const float*         cbhh  = (const float*)d_in[7];
    const float*         sWih  = (const float*)d_in[8];
    const float*         sWhh  = (const float*)d_in[9];
    const float*         sbih  = (const float*)d_in[10];
    const float*         sbhh  = (const float*)d_in[11];
    float* out = (float*)d_out;

    detect_edges_kernel<<<1, 1>>>((const unsigned char*)edges);
    bucket_kernel<<<1, 256>>>(edges);

    dim3 gP(G3 / 64, VV / 64, 2);
    precompute_P_kernel<<<gP, 256>>>(emb, cWih, cbih, cbhh, sWih, sbih, sbhh);

    static int smem_bytes = (2 * 256 * 96 + 256 * 32) * 4;   // 229376
    cudaFuncSetAttribute(persistent_kernel,
                         cudaFuncAttributeMaxDynamicSharedMemorySize, smem_bytes);
    persistent_kernel<<<dim3(8, 17), 512, smem_bytes>>>(
        h0, out, nodes, cWhh, cbhh, sWhh, sbhh);

    cudaMemcpyAsync(out + (size_t)TT * DH, out + (size_t)(TT - 1) * DH,
                    (size_t)DH * sizeof(float), cudaMemcpyDeviceToDevice, 0);
}

// round 16
// speedup vs baseline: 1.1612x; 1.1612x over previous
#include <cuda_runtime.h>
#include <math.h>

#define TT 256
#define DD 512
#define HH 256
#define EE 256
#define VV 8192
#define G3 768           // 3*H
#define DH (DD*HH)

// Scratch (static device globals; no runtime allocation).
__device__ float g_P[2][(size_t)VV * G3];   // emb@Wih^T + biases, [sel][v][3H]
__device__ int   g_perm[TT * DD];           // per-step bucketed row ids
__device__ int   g_cnt1[TT];                // grp1 count per step
__device__ int   g_e_is_i32;
__device__ unsigned int g_arr8[8 * 32];     // per-column arrive counters, 128B apart
__device__ unsigned int g_arrive = 0;       // top-level arrive
__device__ unsigned int g_pad[31];          // pad g_arrive onto its own line
__device__ unsigned int g_go[8 * 32];       // per-column release flags, 128B apart

// ---------------------------------------------------------------------------
// Packed f32x2 helpers
// ---------------------------------------------------------------------------
__device__ __forceinline__ unsigned long long dup2(float b) {
    unsigned long long r;
    asm("mov.b64 %0, {%1, %1};" : "=l"(r) : "r"(__float_as_uint(b)));
    return r;
}
__device__ __forceinline__ void fma2(unsigned long long& acc, unsigned long long a, unsigned long long b) {
    asm("fma.rn.f32x2 %0, %1, %2, %0;" : "+l"(acc) : "l"(a), "l"(b));
}
__device__ __forceinline__ void add2(unsigned long long& acc, unsigned long long o) {
    asm("add.rn.f32x2 %0, %0, %1;" : "+l"(acc) : "l"(o));
}
__device__ __forceinline__ float lo32(unsigned long long v) {
    unsigned int l, h; asm("mov.b64 {%0, %1}, %2;" : "=r"(l), "=r"(h) : "l"(v));
    return __uint_as_float(l);
}
__device__ __forceinline__ float hi32(unsigned long long v) {
    unsigned int l, h; asm("mov.b64 {%0, %1}, %2;" : "=r"(l), "=r"(h) : "l"(v));
    return __uint_as_float(h);
}
__device__ __forceinline__ unsigned int atom_add_acqrel(unsigned int* p) {
    unsigned int o;
    asm volatile("atom.add.acq_rel.gpu.u32 %0, [%1], 1;" : "=r"(o) : "l"(p) : "memory");
    return o;
}
__device__ __forceinline__ unsigned int ld_acquire(const unsigned int* p) {
    unsigned int v;
    asm volatile("ld.acquire.gpu.u32 %0, [%1];" : "=r"(v) : "l"(p) : "memory");
    return v;
}
__device__ __forceinline__ void st_release(unsigned int* p, unsigned int v) {
    asm volatile("st.release.gpu.u32 [%0], %1;" :: "l"(p), "r"(v) : "memory");
}
__device__ __forceinline__ float fast_sigmoid(float x) {
    return 1.f / (1.f + __expf(-x));
}
__device__ __forceinline__ float fast_tanh(float x) {
    return 1.f - 2.f / (__expf(2.f * x) + 1.f);   // exact limits at +-inf, no NaN
}

// ---------------------------------------------------------------------------
__global__ void detect_edges_kernel(const unsigned char* __restrict__ e) {
    int i32 = 1;
    for (int k = 0; k < 256; ++k)
        if (e[4 * k + 1] | e[4 * k + 2] | e[4 * k + 3]) { i32 = 0; break; }
    g_e_is_i32 = i32;
}

__global__ void bucket_kernel(const void* __restrict__ edges) {
    int t = threadIdx.x;
    if (t >= TT) return;
    const int is_i32 = g_e_is_i32;
    const unsigned char* e8  = (const unsigned char*)edges + (size_t)t * DD;
    const int*           e32 = (const int*)edges + (size_t)t * DD;
    int* p = g_perm + (size_t)t * DD;
    int i1 = 0, i0 = 0;
    for (int d = 0; d < DD; ++d) {
        bool ev = is_i32 ? (e32[d] != 0) : (e8[d] != 0);
        if (ev) p[i1++] = d;
        else    p[DD - 1 - (i0++)] = d;
    }
    g_cnt1[t] = i1;
}

// ---------------------------------------------------------------------------
// P[sel][v][j] = dot(emb[v], Wih[j]) + bih[j] + (j < 2H ? bhh[j] : 0)
// 64x64 tile, 256 threads, 4x4 microtile, f32x2-packed row pairs.
// (Single-buffered: the double-buffered variant measured ~130us slower.)
// ---------------------------------------------------------------------------
__global__ void precompute_P_kernel(
    const float* __restrict__ emb,
    const float* __restrict__ cWih, const float* __restrict__ cbih, const float* __restrict__ cbhh,
    const float* __restrict__ sWih, const float* __restrict__ sbih, const float* __restrict__ sbhh)
{
    int sel = blockIdx.z;
    const float* Wih = sel ? cWih : sWih;
    const float* bih = sel ? cbih : sbih;
    const float* bhh = sel ? cbhh : sbhh;
    float* P = g_P[sel];

    __shared__ __align__(16) float As[32][64];
    __shared__ __align__(16) float Bs[32][64];

    int vbase = blockIdx.y * 64;
    int jbase = blockIdx.x * 64;
    int tid  = threadIdx.x;
    int rowg = tid >> 4;
    int colg = tid & 15;

    unsigned long long acc[2][4];
#pragma unroll
    for (int i = 0; i < 2; ++i)
#pragma unroll
        for (int j = 0; j < 4; ++j) acc[i][j] = 0ull;

    for (int kb = 0; kb < EE; kb += 32) {
#pragma unroll
        for (int i = 0; i < 2; ++i) {
            int lin = tid + i * 256;
            int m  = lin >> 3;
            int k4 = (lin & 7) << 2;
            float4 v = *(const float4*)&emb[(size_t)(vbase + m) * EE + kb + k4];
            As[k4 + 0][m] = v.x; As[k4 + 1][m] = v.y; As[k4 + 2][m] = v.z; As[k4 + 3][m] = v.w;
            float4 w = *(const float4*)&Wih[(size_t)(jbase + m) * EE + kb + k4];
            Bs[k4 + 0][m] = w.x; Bs[k4 + 1][m] = w.y; Bs[k4 + 2][m] = w.z; Bs[k4 + 3][m] = w.w;
        }
        __syncthreads();
#pragma unroll 8
        for (int k = 0; k < 32; ++k) {
            ulonglong2 av = *(const ulonglong2*)&As[k][rowg * 4];
            float4 b = *(const float4*)&Bs[k][colg * 4];
            unsigned long long b0 = dup2(b.x), b1 = dup2(b.y), b2 = dup2(b.z), b3 = dup2(b.w);
            fma2(acc[0][0], av.x, b0); fma2(acc[1][0], av.y, b0);
            fma2(acc[0][1], av.x, b1); fma2(acc[1][1], av.y, b1);
            fma2(acc[0][2], av.x, b2); fma2(acc[1][2], av.y, b2);
            fma2(acc[0][3], av.x, b3); fma2(acc[1][3], av.y, b3);
        }
        __syncthreads();
    }

#pragma unroll
    for (int i = 0; i < 2; ++i) {
        int v0 = vbase + rowg * 4 + i * 2;
#pragma unroll
        for (int j = 0; j < 4; ++j) {
            int jj = jbase + colg * 4 + j;
            float bias = bih[jj] + (jj < 2 * HH ? bhh[jj] : 0.f);
            P[(size_t)v0 * G3 + jj]       = lo32(acc[i][j]) + bias;
            P[(size_t)(v0 + 1) * G3 + jj] = hi32(acc[i][j]) + bias;
        }
    }
}

extern __shared__ float dyn_smem[];

// ---------------------------------------------------------------------------
// Persistent recurrent kernel (R14 structure). Grid (8 u-tiles, 17 slots) =
// 136 blocks. Per step: P/hp prefetch, per-quarter gather + named barrier,
// split-K x4 FFMA2 loop (unroll 32), 2-phase combine, t+1 meta prefetch
// above the epilogue, packed-buffer epilogue, two-level grid barrier.
// Barrier release: single releaser broadcasts to 8 per-column go-flags
// (st.release, 128B apart); each column's 17 pollers spin on their own flag
// (17 readers/line instead of 136 on one line).
// ---------------------------------------------------------------------------
__global__ void __launch_bounds__(512, 1) persistent_kernel(
    const float* __restrict__ h0,              // [D,H]
    float* __restrict__ out,                   // [T,D,H]
    const int* __restrict__ nodes,             // [T,D]
    const float* __restrict__ cWhh, const float* __restrict__ cbhh,
    const float* __restrict__ sWhh, const float* __restrict__ sbhh)
{
    float* sB = dyn_smem;                       // [2][256][96]
    float* sA = dyn_smem + 2 * 256 * 96;        // [256][32] swizzled; bufs overlay
    unsigned long long* sPq = (unsigned long long*)sA;

    __shared__ int Rs[2][32];
    __shared__ int Ns[2][32];
    __shared__ unsigned char Vs[2][32];
    __shared__ float s_bnb[2][32];
    __shared__ unsigned int s_e0;

    int tid   = threadIdx.x;
    int u0    = blockIdx.x * 32;
    int slot  = blockIdx.y;
    int q     = tid >> 7;          // K-quarter 0..3
    int qtid  = tid & 127;
    int rowg  = qtid >> 5;         // rows rowg*8..+7
    int colg  = qtid & 31;         // cols colg*3..+2
    int r8    = rowg * 8;
    int qoff  = q << 6;

    // Base flag read at kernel start. All per-column flags hold identical
    // values between launches (releaser writes all 8 equally); launch spread
    // is far smaller than prologue+step0, so no release can precede any
    // block's first instruction.
    if (tid == 0) s_e0 = *(volatile unsigned int*)&g_go[blockIdx.x * 32];

    // ---- prologue: load both Whh slices into smem (once) ----
    for (int g = 0; g < 2; ++g) {
        const float* W = g ? cWhh : sWhh;
        for (int idx = tid; idx < 96 * 64; idx += 512) {
            int c  = idx >> 6;
            int k4 = (idx & 63) << 2;
            int wr = ((c >> 5) << 8) + u0 + (c & 31);
            float4 v = *(const float4*)&W[(size_t)wr * HH + k4];
            float* b = sB + ((size_t)g * 256 + k4) * 96 + c;
            b[0 * 96] = v.x; b[1 * 96] = v.y; b[2 * 96] = v.z; b[3 * 96] = v.w;
        }
    }
    if (tid < 64) {
        int g = tid >> 5, ui = tid & 31;
        s_bnb[g][ui] = (g ? cbhh : sbhh)[2 * HH + u0 + ui];
    }

    // epilogue element assignment: elems e = tid, tid+512 -> rows em0/em1, unit eu
    int em0 = tid >> 5;            // 0..15
    int em1 = em0 + 16;            // 16..31
    int eu  = tid & 31;

    // packed-buffer float offsets (constant per thread):
    // C(m,c) float index = (m>>3)*832 + (c/3)*26 + (c%3)*8 + ((m&7)>>1)*2 + (m&1)
    int gof[3];
#pragma unroll
    for (int g = 0; g < 3; ++g) {
        int c  = g * 32 + eu;
        int cD = c / 3;
        int cM = c - 3 * cD;
        gof[g] = cD * 26 + cM * 8;
    }
    int r0of = (em0 >> 3) * 832 + ((em0 & 7) >> 1) * 2 + (em0 & 1);
    int r1of = (em1 >> 3) * 832 + ((em1 & 7) >> 1) * 2 + (em1 & 1);

    // ---- meta for t = 0 ----
    bool act; int grp;
    {
        int cnt1 = g_cnt1[0];
        int n1 = (cnt1 + 31) >> 5;
        int n0 = (DD - cnt1 + 31) >> 5;
        int pbase = 0;
        if (slot < n1)           { act = true;  grp = 1; pbase = slot * 32; }
        else if (slot < n1 + n0) { act = true;  grp = 0; pbase = DD - (slot - n1 + 1) * 32; }
        else                      { act = false; grp = 0; }
        if (act && tid < 32) {
            int p = pbase + tid;
            bool v = grp ? (p < cnt1) : (p >= cnt1);
            int pp = v ? p : (grp ? 0 : DD - 1);
            int d = g_perm[pp];
            Rs[0][tid] = d;
            Ns[0][tid] = nodes[d];
            Vs[0][tid] = v ? 1 : 0;
        }
    }
    __syncthreads();
    unsigned int e0 = s_e0;

    for (int t = 0; t < TT; ++t) {
        int cur = t & 1;
        const float* h_prev = (t == 0) ? h0 : (out + (size_t)(t - 1) * DH);
        float*       h_out  = out + (size_t)t * DH;

        // next-step activity (cheap ALU; LDGs issued later, post-combine)
        int tn = t + 1;
        bool act2 = false; int grp2 = 0; int pbase2 = 0; int cnt1n = 0;
        if (tn < TT) {
            cnt1n = g_cnt1[tn];
            int n1 = (cnt1n + 31) >> 5;
            int n0 = (DD - cnt1n + 31) >> 5;
            if (slot < n1)           { act2 = true; grp2 = 1; pbase2 = slot * 32; }
            else if (slot < n1 + n0) { act2 = true; grp2 = 0; pbase2 = DD - (slot - n1 + 1) * 32; }
        }

        if (act) {
            // ---- prefetch epilogue operands (overlap with gather + k-loop) ----
            const float* P = g_P[grp];
            const float* Pp0 = P + (size_t)Ns[cur][em0] * G3 + u0;
            const float* Pp1 = P + (size_t)Ns[cur][em1] * G3 + u0;
            float pf_gr0 = __ldg(Pp0 + eu);
            float pf_gz0 = __ldg(Pp0 + HH + eu);
            float pf_gn0 = __ldg(Pp0 + 2 * HH + eu);
            float pf_gr1 = __ldg(Pp1 + eu);
            float pf_gz1 = __ldg(Pp1 + HH + eu);
            float pf_gn1 = __ldg(Pp1 + 2 * HH + eu);
            float pf_hp0 = __ldg(h_prev + (size_t)Rs[cur][em0] * HH + u0 + eu);
            float pf_hp1 = __ldg(h_prev + (size_t)Rs[cur][em1] * HH + u0 + eu);

            // ---- per-quarter gather: 32 rows x 64 k of this quarter ----
#pragma unroll
            for (int i = 0; i < 4; ++i) {
                int lin = i * 128 + qtid;        // 0..511 : 32 rows x 16 float4
                int m   = lin >> 4;
                int k   = qoff + ((lin & 15) << 2);
                float4 v = *(const float4*)&h_prev[(size_t)Rs[cur][m] * HH + k];
                int ms = m ^ (k & 28);
                sA[(k + 0) * 32 + ms] = v.x;
                sA[(k + 1) * 32 + ms] = v.y;
                sA[(k + 2) * 32 + ms] = v.z;
                sA[(k + 3) * 32 + ms] = v.w;
            }
            asm volatile("bar.sync %0, 128;" :: "r"(1 + q) : "memory");

            // ---- split-K x4 FFMA2 loop: this quarter does K=64 ----
            const float* Apt = sA + qoff * 32;
            const float* Bpt = sB + (size_t)grp * (256 * 96) + qoff * 96 + colg * 3;
            unsigned long long acc[3][4];   // [col][row-pair]
#pragma unroll
            for (int jj = 0; jj < 3; ++jj)
#pragma unroll
                for (int p = 0; p < 4; ++p) acc[jj][p] = 0ull;
#pragma unroll 32
            for (int kk = 0; kk < 64; ++kk) {
                int sw = kk & 28;               // compile-time per unrolled slot
                ulonglong2 a01 = *(const ulonglong2*)(Apt + kk * 32 + (r8 ^ sw));
                ulonglong2 a23 = *(const ulonglong2*)(Apt + kk * 32 + ((r8 + 4) ^ sw));
                const float* b = Bpt + kk * 96;
                unsigned long long b0 = dup2(b[0]);
                unsigned long long b1 = dup2(b[1]);
                unsigned long long b2 = dup2(b[2]);
                fma2(acc[0][0], a01.x, b0); fma2(acc[0][1], a01.y, b0);
                fma2(acc[0][2], a23.x, b0); fma2(acc[0][3], a23.y, b0);
                fma2(acc[1][0], a01.x, b1); fma2(acc[1][1], a01.y, b1);
                fma2(acc[1][2], a23.x, b1); fma2(acc[1][3], a23.y, b1);
                fma2(acc[2][0], a01.x, b2); fma2(acc[2][1], a01.y, b2);
                fma2(acc[2][2], a23.x, b2); fma2(acc[2][3], a23.y, b2);
            }
            __syncthreads();     // all sA reads done before buffer overlay

            // ---- combine: q1/q3 write, then q0/q2 add+write, epilogue sums ----
            unsigned long long* bufA = sPq;          // [128][13] u64
            unsigned long long* bufB = sPq + 1664;
            if (q == 1) {
                unsigned long long* wp = bufA + qtid * 13;
#pragma unroll
                for (int jj = 0; jj < 3; ++jj)
#pragma unroll
                    for (int p = 0; p < 4; ++p) wp[jj * 4 + p] = acc[jj][p];
            } else if (q == 3) {
                unsigned long long* wp = bufB + qtid * 13;
#pragma unroll
                for (int jj = 0; jj < 3; ++jj)
#pragma unroll
                    for (int p = 0; p < 4; ++p) wp[jj * 4 + p] = acc[jj][p];
            }
            __syncthreads();
            if (q == 0) {
                unsigned long long* rw = bufA + qtid * 13;
#pragma unroll
                for (int jj = 0; jj < 3; ++jj)
#pragma unroll
                    for (int p = 0; p < 4; ++p) { add2(acc[jj][p], rw[jj * 4 + p]); rw[jj * 4 + p] = acc[jj][p]; }
            } else if (q == 2) {
                unsigned long long* rw = bufB + qtid * 13;
#pragma unroll
                for (int jj = 0; jj < 3; ++jj)
#pragma unroll
                    for (int p = 0; p < 4; ++p) { add2(acc[jj][p], rw[jj * 4 + p]); rw[jj * 4 + p] = acc[jj][p]; }
            }
            __syncthreads();

            // ---- t+1 meta LDGs issued here: latency overlaps the epilogue ----
            if (act2 && tid < 32) {
                int p = pbase2 + tid;
                bool v = grp2 ? (p < cnt1n) : (p >= cnt1n);
                int pp = v ? p : (grp2 ? 0 : DD - 1);
                int d = g_perm[(size_t)tn * DD + pp];
                Rs[tn & 1][tid] = d;
                Ns[tn & 1][tid] = nodes[(size_t)tn * DD + d];
                Vs[tn & 1][tid] = v ? 1 : 0;
            }

            // ---- GRU gate epilogue: C = bufA + bufB, 2 elems per thread ----
            const float* bufAf = (const float*)bufA;
            const float* bufBf = (const float*)bufB;
            if (Vs[cur][em0]) {
                float hr = bufAf[r0of + gof[0]] + bufBf[r0of + gof[0]];
                float hz = bufAf[r0of + gof[1]] + bufBf[r0of + gof[1]];
                float hn = bufAf[r0of + gof[2]] + bufBf[r0of + gof[2]] + s_bnb[grp][eu];
                float r = fast_sigmoid(pf_gr0 + hr);
                float z = fast_sigmoid(pf_gz0 + hz);
                float n = fast_tanh(pf_gn0 + r * hn);
                h_out[(size_t)Rs[cur][em0] * HH + u0 + eu] = (1.f - z) * n + z * pf_hp0;
            }
            if (Vs[cur][em1]) {
                float hr = bufAf[r1of + gof[0]] + bufBf[r1of + gof[0]];
                float hz = bufAf[r1of + gof[1]] + bufBf[r1of + gof[1]];
                float hn = bufAf[r1of + gof[2]] + bufBf[r1of + gof[2]] + s_bnb[grp][eu];
                float r = fast_sigmoid(pf_gr1 + hr);
                float z = fast_sigmoid(pf_gz1 + hz);
                float n = fast_tanh(pf_gn1 + r * hn);
                h_out[(size_t)Rs[cur][em1] * HH + u0 + eu] = (1.f - z) * n + z * pf_hp1;
            }
        } else {
            // inactive this step: still load next-step meta
            if (act2 && tid < 32) {
                int p = pbase2 + tid;
                bool v = grp2 ? (p < cnt1n) : (p >= cnt1n);
                int pp = v ? p : (grp2 ? 0 : DD - 1);
                int d = g_perm[(size_t)tn * DD + pp];
                Rs[tn & 1][tid] = d;
                Ns[tn & 1][tid] = nodes[(size_t)tn * DD + d];
                Vs[tn & 1][tid] = v ? 1 : 0;
            }
        }
        __syncthreads();    // epilogue reads/stores done + next meta visible

        // ---- two-level grid barrier, per-column release flags ----
        if (t < TT - 1) {
            if (tid == 0) {
                unsigned int o = atom_add_acqrel(&g_arr8[blockIdx.x * 32]);
                if (o == 16) {                          // last of 17 in this column
                    g_arr8[blockIdx.x * 32] = 0;        // ordered by next release-RMW
                    unsigned int o2 = atom_add_acqrel(&g_arrive);
                    if (o2 == 7) {                      // last column: broadcast release
                        g_arrive = 0;
                        unsigned int gv = e0 + (unsigned int)(t + 1);
#pragma unroll
                        for (int c = 0; c < 8; ++c)
                            st_release(&g_go[c * 32], gv);
                    }
                }
                while (ld_acquire(&g_go[blockIdx.x * 32]) - e0 < (unsigned int)(t + 1)) { }
            }
            __syncthreads();
        }
        act = act2; grp = grp2;
    }
}

// ---------------------------------------------------------------------------
extern "C" void kernel_launch(void* const* d_in, const int* in_sizes, int n_in,
                              void* d_out, int out_size) {
    const int*           nodes = (const int*)d_in[0];
    const void*          edges = d_in[1];
    const float*         h0    = (const float*)d_in[2];
    const float*         emb   = (const float*)d_in[3];
    const float*         cWih  = (const float*)d_in[4];
    const float*         cWhh  = (const float*)d_in[5];
    const float*         cbih  = (const float*)d_in[6];
    const float*         cbhh  = (const float*)d_in[7];
    const float*         sWih  = (const float*)d_in[8];
    const float*         sWhh  = (const float*)d_in[9];
    const float*         sbih  = (const float*)d_in[10];
    const float*         sbhh  = (const float*)d_in[11];
    float* out = (float*)d_out;

    detect_edges_kernel<<<1, 1>>>((const unsigned char*)edges);
    bucket_kernel<<<1, 256>>>(edges);

    dim3 gP(G3 / 64, VV / 64, 2);
    precompute_P_kernel<<<gP, 256>>>(emb, cWih, cbih, cbhh, sWih, sbih, sbhh);

    static int smem_bytes = (2 * 256 * 96 + 256 * 32) * 4;   // 229376
    cudaFuncSetAttribute(persistent_kernel,
                         cudaFuncAttributeMaxDynamicSharedMemorySize, smem_bytes);
    persistent_kernel<<<dim3(8, 17), 512, smem_bytes>>>(
        h0, out, nodes, cWhh, cbhh, sWhh, sbhh);

    cudaMemcpyAsync(out + (size_t)TT * DH, out + (size_t)(TT - 1) * DH,
                    (size_t)DH * sizeof(float), cudaMemcpyDeviceToDevice, 0);
}

// round 17
// speedup vs baseline: 1.4911x; 1.2840x over previous
#include <cuda_runtime.h>
#include <math.h>

#define TT 256
#define DD 512
#define HH 256
#define EE 256
#define VV 8192
#define G3 768           // 3*H
#define DH (DD*HH)

// Scratch (static device globals; no runtime allocation).
__device__ float g_P[2][(size_t)VV * G3];   // emb@Wih^T + biases, [sel][v][3H]
__device__ int   g_perm[TT * DD];           // per-step bucketed row ids
__device__ int   g_cnt1[TT];                // grp1 count per step
__device__ int   g_e_is_i32;
__device__ unsigned int g_arr8[8 * 32];     // per-column arrive counters, 128B apart
__device__ unsigned int g_arrive = 0;
__device__ unsigned int g_pad[31];          // keep g_epoch on its own 128B line
__device__ unsigned int g_epoch  = 0;

// ---------------------------------------------------------------------------
// Packed f32x2 helpers
// ---------------------------------------------------------------------------
__device__ __forceinline__ unsigned long long dup2(float b) {
    unsigned long long r;
    asm("mov.b64 %0, {%1, %1};" : "=l"(r) : "r"(__float_as_uint(b)));
    return r;
}
__device__ __forceinline__ void fma2(unsigned long long& acc, unsigned long long a, unsigned long long b) {
    asm("fma.rn.f32x2 %0, %1, %2, %0;" : "+l"(acc) : "l"(a), "l"(b));
}
__device__ __forceinline__ void add2(unsigned long long& acc, unsigned long long o) {
    asm("add.rn.f32x2 %0, %0, %1;" : "+l"(acc) : "l"(o));
}
__device__ __forceinline__ float lo32(unsigned long long v) {
    unsigned int l, h; asm("mov.b64 {%0, %1}, %2;" : "=r"(l), "=r"(h) : "l"(v));
    return __uint_as_float(l);
}
__device__ __forceinline__ float hi32(unsigned long long v) {
    unsigned int l, h; asm("mov.b64 {%0, %1}, %2;" : "=r"(l), "=r"(h) : "l"(v));
    return __uint_as_float(h);
}
__device__ __forceinline__ unsigned int atom_add_acqrel(unsigned int* p) {
    unsigned int o;
    asm volatile("atom.add.acq_rel.gpu.u32 %0, [%1], 1;" : "=r"(o) : "l"(p) : "memory");
    return o;
}
__device__ __forceinline__ unsigned int ld_acquire(const unsigned int* p) {
    unsigned int v;
    asm volatile("ld.acquire.gpu.u32 %0, [%1];" : "=r"(v) : "l"(p) : "memory");
    return v;
}
__device__ __forceinline__ float fast_sigmoid(float x) {
    return 1.f / (1.f + __expf(-x));
}
__device__ __forceinline__ float fast_tanh(float x) {
    return 1.f - 2.f / (__expf(2.f * x) + 1.f);   // exact limits at +-inf, no NaN
}

// ---------------------------------------------------------------------------
__global__ void detect_edges_kernel(const unsigned char* __restrict__ e) {
    int i32 = 1;
    for (int k = 0; k < 256; ++k)
        if (e[4 * k + 1] | e[4 * k + 2] | e[4 * k + 3]) { i32 = 0; break; }
    g_e_is_i32 = i32;
}

// Warp-parallel bucketing: one warp per timestep, ballot/popc prefix over 16
// chunks of 32. Output layout identical to the serial version: grp1 rows
// ascending from slot 0, grp0 rows (ascending d) filling from slot 511 down.
__global__ void bucket_kernel(const void* __restrict__ edges) {
    int t    = blockIdx.x;
    int lane = threadIdx.x;        // 0..31
    const int is_i32 = g_e_is_i32;
    const unsigned char* e8  = (const unsigned char*)edges + (size_t)t * DD;
    const int*           e32 = (const int*)edges + (size_t)t * DD;
    int* p = g_perm + (size_t)t * DD;
    unsigned int lt = (1u << lane) - 1u;
    int i1 = 0, i0 = 0;
#pragma unroll
    for (int c = 0; c < 16; ++c) {
        int d = c * 32 + lane;
        bool ev = is_i32 ? (e32[d] != 0) : (e8[d] != 0);
        unsigned int mask = __ballot_sync(0xffffffffu, ev);
        int pre1 = __popc(mask & lt);
        int pre0 = __popc(~mask & lt);
        if (ev) p[i1 + pre1] = d;
        else    p[DD - 1 - (i0 + pre0)] = d;
        int n1 = __popc(mask);
        i1 += n1;
        i0 += 32 - n1;
    }
    if (lane == 0) g_cnt1[t] = i1;
}

// ---------------------------------------------------------------------------
// P[sel][v][j] = dot(emb[v], Wih[j]) + bih[j] + (j < 2H ? bhh[j] : 0)
// 64x64 tile, 256 threads, 4x4 microtile, f32x2-packed row pairs.
// ---------------------------------------------------------------------------
__global__ void precompute_P_kernel(
    const float* __restrict__ emb,
    const float* __restrict__ cWih, const float* __restrict__ cbih, const float* __restrict__ cbhh,
    const float* __restrict__ sWih, const float* __restrict__ sbih, const float* __restrict__ sbhh)
{
    int sel = blockIdx.z;
    const float* Wih = sel ? cWih : sWih;
    const float* bih = sel ? cbih : sbih;
    const float* bhh = sel ? cbhh : sbhh;
    float* P = g_P[sel];

    __shared__ __align__(16) float As[32][64];
    __shared__ __align__(16) float Bs[32][64];

    int vbase = blockIdx.y * 64;
    int jbase = blockIdx.x * 64;
    int tid  = threadIdx.x;
    int rowg = tid >> 4;
    int colg = tid & 15;

    unsigned long long acc[2][4];
#pragma unroll
    for (int i = 0; i < 2; ++i)
#pragma unroll
        for (int j = 0; j < 4; ++j) acc[i][j] = 0ull;

    for (int kb = 0; kb < EE; kb += 32) {
#pragma unroll
        for (int i = 0; i < 2; ++i) {
            int lin = tid + i * 256;
            int m  = lin >> 3;
            int k4 = (lin & 7) << 2;
            float4 v = *(const float4*)&emb[(size_t)(vbase + m) * EE + kb + k4];
            As[k4 + 0][m] = v.x; As[k4 + 1][m] = v.y; As[k4 + 2][m] = v.z; As[k4 + 3][m] = v.w;
            float4 w = *(const float4*)&Wih[(size_t)(jbase + m) * EE + kb + k4];
            Bs[k4 + 0][m] = w.x; Bs[k4 + 1][m] = w.y; Bs[k4 + 2][m] = w.z; Bs[k4 + 3][m] = w.w;
        }
        __syncthreads();
#pragma unroll 8
        for (int k = 0; k < 32; ++k) {
            ulonglong2 av = *(const ulonglong2*)&As[k][rowg * 4];
            float4 b = *(const float4*)&Bs[k][colg * 4];
            unsigned long long b0 = dup2(b.x), b1 = dup2(b.y), b2 = dup2(b.z), b3 = dup2(b.w);
            fma2(acc[0][0], av.x, b0); fma2(acc[1][0], av.y, b0);
            fma2(acc[0][1], av.x, b1); fma2(acc[1][1], av.y, b1);
            fma2(acc[0][2], av.x, b2); fma2(acc[1][2], av.y, b2);
            fma2(acc[0][3], av.x, b3); fma2(acc[1][3], av.y, b3);
        }
        __syncthreads();
    }

#pragma unroll
    for (int i = 0; i < 2; ++i) {
        int v0 = vbase + rowg * 4 + i * 2;
#pragma unroll
        for (int j = 0; j < 4; ++j) {
            int jj = jbase + colg * 4 + j;
            float bias = bih[jj] + (jj < 2 * HH ? bhh[jj] : 0.f);
            P[(size_t)v0 * G3 + jj]       = lo32(acc[i][j]) + bias;
            P[(size_t)(v0 + 1) * G3 + jj] = hi32(acc[i][j]) + bias;
        }
    }
}

extern __shared__ float dyn_smem[];

// ---------------------------------------------------------------------------
// Persistent recurrent kernel (R14, byte-identical). Grid (8 u-tiles, 17
// slots) = 136 blocks. Per step: P/hp prefetch, per-quarter gather + named
// barrier, split-K x4 FFMA2 loop (unroll 32), 2-phase combine, t+1 meta
// prefetch above the epilogue, packed-buffer epilogue, acq_rel two-level
// grid barrier with 128B-spaced column counters.
// ---------------------------------------------------------------------------
__global__ void __launch_bounds__(512, 1) persistent_kernel(
    const float* __restrict__ h0,              // [D,H]
    float* __restrict__ out,                   // [T,D,H]
    const int* __restrict__ nodes,             // [T,D]
    const float* __restrict__ cWhh, const float* __restrict__ cbhh,
    const float* __restrict__ sWhh, const float* __restrict__ sbhh)
{
    float* sB = dyn_smem;                       // [2][256][96]
    float* sA = dyn_smem + 2 * 256 * 96;        // [256][32] swizzled; bufs overlay
    unsigned long long* sPq = (unsigned long long*)sA;

    __shared__ int Rs[2][32];
    __shared__ int Ns[2][32];
    __shared__ unsigned char Vs[2][32];
    __shared__ float s_bnb[2][32];
    __shared__ unsigned int s_e0;

    int tid   = threadIdx.x;
    int u0    = blockIdx.x * 32;
    int slot  = blockIdx.y;
    int q     = tid >> 7;          // K-quarter 0..3
    int qtid  = tid & 127;
    int rowg  = qtid >> 5;         // rows rowg*8..+7
    int colg  = qtid & 31;         // cols colg*3..+2
    int r8    = rowg * 8;
    int qoff  = q << 6;

    if (tid == 0) s_e0 = *(volatile unsigned int*)&g_epoch;

    // ---- prologue: load both Whh slices into smem (once) ----
    for (int g = 0; g < 2; ++g) {
        const float* W = g ? cWhh : sWhh;
        for (int idx = tid; idx < 96 * 64; idx += 512) {
            int c  = idx >> 6;
            int k4 = (idx & 63) << 2;
            int wr = ((c >> 5) << 8) + u0 + (c & 31);
            float4 v = *(const float4*)&W[(size_t)wr * HH + k4];
            float* b = sB + ((size_t)g * 256 + k4) * 96 + c;
            b[0 * 96] = v.x; b[1 * 96] = v.y; b[2 * 96] = v.z; b[3 * 96] = v.w;
        }
    }
    if (tid < 64) {
        int g = tid >> 5, ui = tid & 31;
        s_bnb[g][ui] = (g ? cbhh : sbhh)[2 * HH + u0 + ui];
    }

    // epilogue element assignment: elems e = tid, tid+512 -> rows em0/em1, unit eu
    int em0 = tid >> 5;            // 0..15
    int em1 = em0 + 16;            // 16..31
    int eu  = tid & 31;

    // packed-buffer float offsets (constant per thread):
    // C(m,c) float index = (m>>3)*832 + (c/3)*26 + (c%3)*8 + ((m&7)>>1)*2 + (m&1)
    int gof[3];
#pragma unroll
    for (int g = 0; g < 3; ++g) {
        int c  = g * 32 + eu;
        int cD = c / 3;
        int cM = c - 3 * cD;
        gof[g] = cD * 26 + cM * 8;
    }
    int r0of = (em0 >> 3) * 832 + ((em0 & 7) >> 1) * 2 + (em0 & 1);
    int r1of = (em1 >> 3) * 832 + ((em1 & 7) >> 1) * 2 + (em1 & 1);

    // ---- meta for t = 0 ----
    bool act; int grp;
    {
        int cnt1 = g_cnt1[0];
        int n1 = (cnt1 + 31) >> 5;
        int n0 = (DD - cnt1 + 31) >> 5;
        int pbase = 0;
        if (slot < n1)           { act = true;  grp = 1; pbase = slot * 32; }
        else if (slot < n1 + n0) { act = true;  grp = 0; pbase = DD - (slot - n1 + 1) * 32; }
        else                      { act = false; grp = 0; }
        if (act && tid < 32) {
            int p = pbase + tid;
            bool v = grp ? (p < cnt1) : (p >= cnt1);
            int pp = v ? p : (grp ? 0 : DD - 1);
            int d = g_perm[pp];
            Rs[0][tid] = d;
            Ns[0][tid] = nodes[d];
            Vs[0][tid] = v ? 1 : 0;
        }
    }
    __syncthreads();
    unsigned int e0 = s_e0;

    for (int t = 0; t < TT; ++t) {
        int cur = t & 1;
        const float* h_prev = (t == 0) ? h0 : (out + (size_t)(t - 1) * DH);
        float*       h_out  = out + (size_t)t * DH;

        // next-step activity (cheap ALU; LDGs issued later, post-combine)
        int tn = t + 1;
        bool act2 = false; int grp2 = 0; int pbase2 = 0; int cnt1n = 0;
        if (tn < TT) {
            cnt1n = g_cnt1[tn];
            int n1 = (cnt1n + 31) >> 5;
            int n0 = (DD - cnt1n + 31) >> 5;
            if (slot < n1)           { act2 = true; grp2 = 1; pbase2 = slot * 32; }
            else if (slot < n1 + n0) { act2 = true; grp2 = 0; pbase2 = DD - (slot - n1 + 1) * 32; }
        }

        if (act) {
            // ---- prefetch epilogue operands (overlap with gather + k-loop) ----
            const float* P = g_P[grp];
            const float* Pp0 = P + (size_t)Ns[cur][em0] * G3 + u0;
            const float* Pp1 = P + (size_t)Ns[cur][em1] * G3 + u0;
            float pf_gr0 = __ldg(Pp0 + eu);
            float pf_gz0 = __ldg(Pp0 + HH + eu);
            float pf_gn0 = __ldg(Pp0 + 2 * HH + eu);
            float pf_gr1 = __ldg(Pp1 + eu);
            float pf_gz1 = __ldg(Pp1 + HH + eu);
            float pf_gn1 = __ldg(Pp1 + 2 * HH + eu);
            float pf_hp0 = __ldg(h_prev + (size_t)Rs[cur][em0] * HH + u0 + eu);
            float pf_hp1 = __ldg(h_prev + (size_t)Rs[cur][em1] * HH + u0 + eu);

            // ---- per-quarter gather: 32 rows x 64 k of this quarter ----
#pragma unroll
            for (int i = 0; i < 4; ++i) {
                int lin = i * 128 + qtid;        // 0..511 : 32 rows x 16 float4
                int m   = lin >> 4;
                int k   = qoff + ((lin & 15) << 2);
                float4 v = *(const float4*)&h_prev[(size_t)Rs[cur][m] * HH + k];
                int ms = m ^ (k & 28);
                sA[(k + 0) * 32 + ms] = v.x;
                sA[(k + 1) * 32 + ms] = v.y;
                sA[(k + 2) * 32 + ms] = v.z;
                sA[(k + 3) * 32 + ms] = v.w;
            }
            asm volatile("bar.sync %0, 128;" :: "r"(1 + q) : "memory");

            // ---- split-K x4 FFMA2 loop: this quarter does K=64 ----
            const float* Apt = sA + qoff * 32;
            const float* Bpt = sB + (size_t)grp * (256 * 96) + qoff * 96 + colg * 3;
            unsigned long long acc[3][4];   // [col][row-pair]
#pragma unroll
            for (int jj = 0; jj < 3; ++jj)
#pragma unroll
                for (int p = 0; p < 4; ++p) acc[jj][p] = 0ull;
#pragma unroll 32
            for (int kk = 0; kk < 64; ++kk) {
                int sw = kk & 28;               // compile-time per unrolled slot
                ulonglong2 a01 = *(const ulonglong2*)(Apt + kk * 32 + (r8 ^ sw));
                ulonglong2 a23 = *(const ulonglong2*)(Apt + kk * 32 + ((r8 + 4) ^ sw));
                const float* b = Bpt + kk * 96;
                unsigned long long b0 = dup2(b[0]);
                unsigned long long b1 = dup2(b[1]);
                unsigned long long b2 = dup2(b[2]);
                fma2(acc[0][0], a01.x, b0); fma2(acc[0][1], a01.y, b0);
                fma2(acc[0][2], a23.x, b0); fma2(acc[0][3], a23.y, b0);
                fma2(acc[1][0], a01.x, b1); fma2(acc[1][1], a01.y, b1);
                fma2(acc[1][2], a23.x, b1); fma2(acc[1][3], a23.y, b1);
                fma2(acc[2][0], a01.x, b2); fma2(acc[2][1], a01.y, b2);
                fma2(acc[2][2], a23.x, b2); fma2(acc[2][3], a23.y, b2);
            }
            __syncthreads();     // all sA reads done before buffer overlay

            // ---- combine: q1/q3 write, then q0/q2 add+write, epilogue sums ----
            unsigned long long* bufA = sPq;          // [128][13] u64
            unsigned long long* bufB = sPq + 1664;
            if (q == 1) {
                unsigned long long* wp = bufA + qtid * 13;
#pragma unroll
                for (int jj = 0; jj < 3; ++jj)
#pragma unroll
                    for (int p = 0; p < 4; ++p) wp[jj * 4 + p] = acc[jj][p];
            } else if (q == 3) {
                unsigned long long* wp = bufB + qtid * 13;
#pragma unroll
                for (int jj = 0; jj < 3; ++jj)
#pragma unroll
                    for (int p = 0; p < 4; ++p) wp[jj * 4 + p] = acc[jj][p];
            }
            __syncthreads();
            if (q == 0) {
                unsigned long long* rw = bufA + qtid * 13;
#pragma unroll
                for (int jj = 0; jj < 3; ++jj)
#pragma unroll
                    for (int p = 0; p < 4; ++p) { add2(acc[jj][p], rw[jj * 4 + p]); rw[jj * 4 + p] = acc[jj][p]; }
            } else if (q == 2) {
                unsigned long long* rw = bufB + qtid * 13;
#pragma unroll
                for (int jj = 0; jj < 3; ++jj)
#pragma unroll
                    for (int p = 0; p < 4; ++p) { add2(acc[jj][p], rw[jj * 4 + p]); rw[jj * 4 + p] = acc[jj][p]; }
            }
            __syncthreads();

            // ---- t+1 meta LDGs issued here: latency overlaps the epilogue ----
            if (act2 && tid < 32) {
                int p = pbase2 + tid;
                bool v = grp2 ? (p < cnt1n) : (p >= cnt1n);
                int pp = v ? p : (grp2 ? 0 : DD - 1);
                int d = g_perm[(size_t)tn * DD + pp];
                Rs[tn & 1][tid] = d;
                Ns[tn & 1][tid] = nodes[(size_t)tn * DD + d];
                Vs[tn & 1][tid] = v ? 1 : 0;
            }

            // ---- GRU gate epilogue: C = bufA + bufB, 2 elems per thread ----
            const float* bufAf = (const float*)bufA;
            const float* bufBf = (const float*)bufB;
            if (Vs[cur][em0]) {
                float hr = bufAf[r0of + gof[0]] + bufBf[r0of + gof[0]];
                float hz = bufAf[r0of + gof[1]] + bufBf[r0of + gof[1]];
                float hn = bufAf[r0of + gof[2]] + bufBf[r0of + gof[2]] + s_bnb[grp][eu];
                float r = fast_sigmoid(pf_gr0 + hr);
                float z = fast_sigmoid(pf_gz0 + hz);
                float n = fast_tanh(pf_gn0 + r * hn);
                h_out[(size_t)Rs[cur][em0] * HH + u0 + eu] = (1.f - z) * n + z * pf_hp0;
            }
            if (Vs[cur][em1]) {
                float hr = bufAf[r1of + gof[0]] + bufBf[r1of + gof[0]];
                float hz = bufAf[r1of + gof[1]] + bufBf[r1of + gof[1]];
                float hn = bufAf[r1of + gof[2]] + bufBf[r1of + gof[2]] + s_bnb[grp][eu];
                float r = fast_sigmoid(pf_gr1 + hr);
                float z = fast_sigmoid(pf_gz1 + hz);
                float n = fast_tanh(pf_gn1 + r * hn);
                h_out[(size_t)Rs[cur][em1] * HH + u0 + eu] = (1.f - z) * n + z * pf_hp1;
            }
        } else {
            // inactive this step: still load next-step meta
            if (act2 && tid < 32) {
                int p = pbase2 + tid;
                bool v = grp2 ? (p < cnt1n) : (p >= cnt1n);
                int pp = v ? p : (grp2 ? 0 : DD - 1);
                int d = g_perm[(size_t)tn * DD + pp];
                Rs[tn & 1][tid] = d;
                Ns[tn & 1][tid] = nodes[(size_t)tn * DD + d];
                Vs[tn & 1][tid] = v ? 1 : 0;
            }
        }
        __syncthreads();    // epilogue reads/stores done + next meta visible

        // ---- acq_rel two-level grid barrier (skip after final step) ----
        if (t < TT - 1) {
            if (tid == 0) {
                unsigned int o = atom_add_acqrel(&g_arr8[blockIdx.x * 32]);
                if (o == 16) {                          // last of 17 in this column
                    g_arr8[blockIdx.x * 32] = 0;        // ordered by next release-RMW
                    unsigned int o2 = atom_add_acqrel(&g_arrive);
                    if (o2 == 7) {                      // last column
                        g_arrive = 0;
                        atom_add_acqrel(&g_epoch);
                    }
                }
                while (ld_acquire(&g_epoch) - e0 < (unsigned int)(t + 1)) { }
            }
            __syncthreads();
        }
        act = act2; grp = grp2;
    }
}

// ---------------------------------------------------------------------------
extern "C" void kernel_launch(void* const* d_in, const int* in_sizes, int n_in,
                              void* d_out, int out_size) {
    const int*           nodes = (const int*)d_in[0];
    const void*          edges = d_in[1];
    const float*         h0    = (const float*)d_in[2];
    const float*         emb   = (const float*)d_in[3];
    const float*         cWih  = (const float*)d_in[4];
    const float*         cWhh  = (const float*)d_in[5];
    const float*         cbih  = (const float*)d_in[6];
    const float*         cbhh  = (const float*)d_in[7];
    const float*         sWih  = (const float*)d_in[8];
    const float*         sWhh  = (const float*)d_in[9];
    const float*         sbih  = (const float*)d_in[10];
    const float*         sbhh  = (const float*)d_in[11];
    float* out = (float*)d_out;

    detect_edges_kernel<<<1, 1>>>((const unsigned char*)edges);
    bucket_kernel<<<TT, 32>>>(edges);

    dim3 gP(G3 / 64, VV / 64, 2);
    precompute_P_kernel<<<gP, 256>>>(emb, cWih, cbih, cbhh, sWih, sbih, sbhh);

    static int smem_bytes = (2 * 256 * 96 + 256 * 32) * 4;   // 229376
    cudaFuncSetAttribute(persistent_kernel,
                         cudaFuncAttributeMaxDynamicSharedMemorySize, smem_bytes);
    persistent_kernel<<<dim3(8, 17), 512, smem_bytes>>>(
        h0, out, nodes, cWhh, cbhh, sWhh, sbhh);

    cudaMemcpyAsync(out + (size_t)TT * DH, out + (size_t)(TT - 1) * DH,
                    (size_t)DH * sizeof(float), cudaMemcpyDeviceToDevice, 0);
}